// round 17
// baseline (speedup 1.0000x reference)
#include <cuda_runtime.h>
#include <cstdint>
#include <math.h>

#define B    16
#define H    512
#define V    32000
#define NL   2
#define NBLK 148           // persistent blocks, all co-resident
#define NLSTM_BLK 128      // LSTM j-map uses exactly 128 blocks
#define NTHR 512           // 16 warps/SM
#define ROWS_TOT 217       // 148 * 217 = 32116 >= V (tail masked)
#define RP_MAX 108         // row-pairs 0..108 cover rows 0..217
#define WCHUNK 32          // logits K-chunk (floats)
#define NCHUNK (H / WCHUNK)        // 16
#define WPADF  36          // W tile row stride (floats): lanes 4*rp banks, distinct
#define WROWS2 109         // rows per even/odd tile
#define WTILE  (WROWS2 * WPADF)    // 3924 floats
#define WBUF   (2 * WTILE)         // 7848 floats per buffer (even+odd tiles)

typedef unsigned long long u64;

// dyn smem (floats): LSTM s_in=[0,8192) s_h=[8192,16384); logits h_s=[0,8192)
// (XOR-swizzled in place), W_s=[16384, 16384+2*WBUF)
#define DYN_FLOATS (16384 + 2 * WBUF)
#define SMEM_BYTES (DYN_FLOATS * 4)

// ---------------- device state ----------------
__device__ float g_h[2][NL][B][H];     // ping-pong hidden state
__device__ u64 g_amax[2][B];           // double-buffered argmax accumulator
__device__ unsigned g_cnt;             // full-grid barrier counter (monotonic)
__device__ unsigned g_cnt_lstm;        // LSTM-only barrier counter

// ---------------- packed f32x2 helpers ----------------
__device__ __forceinline__ u64 fma2(u64 a, u64 b, u64 c) {
    u64 d; asm("fma.rn.f32x2 %0,%1,%2,%3;" : "=l"(d) : "l"(a), "l"(b), "l"(c));
    return d;
}
__device__ __forceinline__ u64 add2(u64 a, u64 b) {
    u64 d; asm("add.rn.f32x2 %0,%1,%2;" : "=l"(d) : "l"(a), "l"(b));
    return d;
}
__device__ __forceinline__ float2 unpk(u64 a) {
    float2 r; asm("mov.b64 {%0,%1},%2;" : "=f"(r.x), "=f"(r.y) : "l"(a));
    return r;
}
__device__ __forceinline__ float sigm(float x) { return 1.f / (1.f + expf(-x)); }

// ---------------- cp.async helpers ----------------
__device__ __forceinline__ void cpa16(uint32_t dst, const void* src) {
    asm volatile("cp.async.cg.shared.global [%0], [%1], 16;"
                 :: "r"(dst), "l"(src));
}
#define CP_COMMIT() asm volatile("cp.async.commit_group;")
#define CP_WAIT0()  asm volatile("cp.async.wait_group 0;")

// ---------------- barriers: release-add / acquire-spin, one address each ----
__device__ __forceinline__ void bar_spin(unsigned* cnt, unsigned need) {
    __syncthreads();
    if (threadIdx.x == 0) {
        asm volatile("red.release.gpu.global.add.u32 [%0], 1;"
                     :: "l"(cnt) : "memory");
        unsigned v;
        for (;;) {
            asm volatile("ld.acquire.gpu.global.u32 %0, [%1];"
                         : "=r"(v) : "l"(cnt) : "memory");
            if (v >= need) break;
            __nanosleep(64);
        }
    }
    __syncthreads();
}

// ---------------- init ----------------
__global__ void init_kernel() {
    int tid = blockIdx.x * blockDim.x + threadIdx.x;
    int stride = gridDim.x * blockDim.x;
    float* p = &g_h[0][0][0][0];
    for (int i = tid; i < 2 * NL * B * H; i += stride) p[i] = 0.f;
    if (blockIdx.x == 0 && threadIdx.x < 2 * B)
        (&g_amax[0][0])[threadIdx.x] = 0ull;
    if (blockIdx.x == 0 && threadIdx.x == 0) { g_cnt = 0u; g_cnt_lstm = 0u; }
}

// ---------------- persistent decoder ----------------
__global__ __launch_bounds__(NTHR, 1) void decoder_kernel(
    const float* __restrict__ x,   const float* __restrict__ Wt,
    const float* __restrict__ bp,  const float* __restrict__ Wih,
    const float* __restrict__ Whh, const float* __restrict__ bih,
    const float* __restrict__ bhh, float* __restrict__ out, int T)
{
    extern __shared__ __align__(16) float dyn[];
    __shared__ float s_part[2][2][4][4][8];   // [side][bhalf][jl][gate][b8]
    __shared__ u64 s_best[B][16];

    const int tid  = threadIdx.x;
    const int bx   = blockIdx.x;
    const int lane = tid & 31;
    const int warp = tid >> 5;

    // ---- LSTM role (blocks < 128): warp = (side, bhalf, jl) ----
    const int w_jl    = warp & 3;
    const int w_bh    = (warp >> 2) & 1;
    const int w_side  = warp >> 3;
    const int j       = bx * 4 + w_jl;        // valid when bx < NLSTM_BLK

    // ---- logits role: thread = (row-pair rp, batch-quad bq) ----
    const int v0    = bx * ROWS_TOT;
    const int rp    = tid >> 2;               // 0..127
    const int rp_c  = (rp <= RP_MAX) ? rp : RP_MAX;   // clamp, uniform in-bounds
    const int bq    = tid & 3;                // batches bq*4 .. bq*4+3

    float* const s_in = dyn;                  // [16][512]
    float* const s_h  = dyn + 8192;           // [16][512]
    float* const h_s  = dyn;                  // [16][512] XOR-swizzled (logits)
    float* const W_s  = dyn + 16384;          // [2][even|odd][109][36]

    float c_reg[2] = {0.f, 0.f};              // cell state, fixed per thread
    unsigned full_t = 0;

#pragma unroll 1
    for (int t = 0; t < T; t++) {
        const int p = t & 1;                  // h read side; write side 1-p

        // ---- prefetch logits W chunk 0 (split tiles) under the LSTM phase
        for (int idx = tid; idx < 218 * 8; idx += NTHR) {
            int row = idx >> 3, seg = idx & 7;
            int rg = v0 + row; if (rg > V - 1) rg = V - 1;
            cpa16((uint32_t)__cvta_generic_to_shared(
                      W_s + (row & 1) * WTILE + (row >> 1) * WPADF + seg * 4),
                  Wt + (size_t)rg * H + seg * 4);
        }
        CP_COMMIT();

        // ================= LSTM layers (blocks < 128) =================
#pragma unroll
        for (int layer = 0; layer < NL; layer++) {
            if (bx < NLSTM_BLK) {
                // ---- stage input + recurrent h for ALL 16 batches ----
                for (int i = tid; i < 2048; i += NTHR) {
                    int b = i >> 7, c4 = i & 127;
                    const float4* srcp;
                    if (layer == 0) {
                        if (t == 0) {
                            srcp = (const float4*)(x + (size_t)b * H) + c4;
                        } else {
                            u64 am;
                            asm volatile("ld.global.cg.u64 %0,[%1];"
                                         : "=l"(am) : "l"(&g_amax[1 - p][b])
                                         : "memory");
                            unsigned idx = ~(unsigned)am;
                            if (idx >= V) idx = 0;          // defensive
                            srcp = (const float4*)(Wt + (size_t)idx * H) + c4;
                        }
                    } else {
                        srcp = (const float4*)(&g_h[1 - p][0][b][0]) + c4;
                    }
                    ((float4*)s_in)[i] = __ldcg(srcp);
                    ((float4*)s_h)[i] =
                        __ldcg((const float4*)(&g_h[p][layer][b][0]) + c4);
                }
                __syncthreads();

                // ---- partial dot: 4 gates x 8 batches, one W-side per warp
                const float* Wsel = (w_side ? Whh : Wih) + (size_t)layer * 4 * H * H;
                const float* ssel = (w_side ? s_h : s_in) + (w_bh << 3) * H;

                u64 acc[4][8];
#pragma unroll
                for (int g = 0; g < 4; g++)
#pragma unroll
                    for (int b8 = 0; b8 < 8; b8++) acc[g][b8] = 0ull;

#pragma unroll
                for (int c = 0; c < 4; c++) {
                    const int koff = c * 128 + lane * 4;
                    ulonglong2 w0 = *(const ulonglong2*)(Wsel + (size_t)(0 * H + j) * H + koff);
                    ulonglong2 w1 = *(const ulonglong2*)(Wsel + (size_t)(1 * H + j) * H + koff);
                    ulonglong2 w2 = *(const ulonglong2*)(Wsel + (size_t)(2 * H + j) * H + koff);
                    ulonglong2 w3 = *(const ulonglong2*)(Wsel + (size_t)(3 * H + j) * H + koff);
#pragma unroll
                    for (int b8 = 0; b8 < 8; b8++) {
                        ulonglong2 sv = *(const ulonglong2*)(ssel + (b8 << 9) + koff);
                        acc[0][b8] = fma2(w0.x, sv.x, acc[0][b8]);
                        acc[0][b8] = fma2(w0.y, sv.y, acc[0][b8]);
                        acc[1][b8] = fma2(w1.x, sv.x, acc[1][b8]);
                        acc[1][b8] = fma2(w1.y, sv.y, acc[1][b8]);
                        acc[2][b8] = fma2(w2.x, sv.x, acc[2][b8]);
                        acc[2][b8] = fma2(w2.y, sv.y, acc[2][b8]);
                        acc[3][b8] = fma2(w3.x, sv.x, acc[3][b8]);
                        acc[3][b8] = fma2(w3.y, sv.y, acc[3][b8]);
                    }
                }
                // ---- warp tree reduce (lane 0 gets the k-sum) ----
#pragma unroll
                for (int off = 16; off >= 1; off >>= 1) {
#pragma unroll
                    for (int g = 0; g < 4; g++)
#pragma unroll
                        for (int b8 = 0; b8 < 8; b8++)
                            acc[g][b8] = add2(acc[g][b8],
                                __shfl_down_sync(0xffffffffu, acc[g][b8], off));
                }
                if (lane == 0) {
#pragma unroll
                    for (int g = 0; g < 4; g++)
#pragma unroll
                        for (int b8 = 0; b8 < 8; b8++) {
                            float2 f = unpk(acc[g][b8]);
                            s_part[w_side][w_bh][w_jl][g][b8] = f.x + f.y;
                        }
                }
                __syncthreads();

                // ---- activations: tid<64 owns cell (layer, b, j2) ----
                if (tid < 64) {
                    int b8a = tid & 7, jla = (tid >> 3) & 3, bha = tid >> 5;
                    int b  = bha * 8 + b8a;
                    int j2 = bx * 4 + jla;
                    const float* bi = bih + (size_t)layer * 4 * H;
                    const float* bh = bhh + (size_t)layer * 4 * H;
                    float gi = s_part[0][bha][jla][0][b8a] + s_part[1][bha][jla][0][b8a]
                             + bi[0 * H + j2] + bh[0 * H + j2];
                    float gf = s_part[0][bha][jla][1][b8a] + s_part[1][bha][jla][1][b8a]
                             + bi[1 * H + j2] + bh[1 * H + j2];
                    float gg = s_part[0][bha][jla][2][b8a] + s_part[1][bha][jla][2][b8a]
                             + bi[2 * H + j2] + bh[2 * H + j2];
                    float go = s_part[0][bha][jla][3][b8a] + s_part[1][bha][jla][3][b8a]
                             + bi[3 * H + j2] + bh[3 * H + j2];
                    float cn = sigm(gf) * c_reg[layer] + sigm(gi) * tanhf(gg);
                    float hn = sigm(go) * tanhf(cn);
                    c_reg[layer] = cn;
                    g_h[1 - p][layer][b][j2] = hn;
                }
                // layer-0 handoff is LSTM-internal: 128-block barrier only
                if (layer == 0) bar_spin(&g_cnt_lstm, NLSTM_BLK * (t + 1));
            }
            if (layer == 1) bar_spin(&g_cnt, NBLK * (++full_t));
        }

        // ================= logits + argmax (2x4 reg tile, swizzled h) ======
        {
            // reset the OTHER amax slot for step t+1
            if (bx == 0 && tid < B) atomicExch(&g_amax[1 - p][tid], 0ull);

            // stage h1 [16][512] XOR-swizzled: slot = b*128 + (k4 ^ (b>>2))
            const float4* hp = (const float4*)(&g_h[1 - p][1][0][0]);
            for (int i = tid; i < 2048; i += NTHR) {
                int b = i >> 7, k4 = i & 127;
                *(float4*)(h_s + (b << 9) + ((k4 ^ (b >> 2)) << 2)) = __ldcg(hp + i);
            }

            u64 acc[2][4];                     // [row-in-pair][batch-in-quad]
#pragma unroll
            for (int r = 0; r < 2; r++)
#pragma unroll
                for (int i = 0; i < 4; i++) acc[r][i] = 0ull;

#pragma unroll 1
            for (int kc = 0; kc < NCHUNK; kc++) {
                CP_WAIT0();
                __syncthreads();                 // chunk kc + h staging visible
                if (kc + 1 < NCHUNK) {           // prefetch kc+1 -> other buffer
                    float* Wn = W_s + ((kc + 1) & 1) * WBUF;
                    const float* gsrc = Wt + (size_t)(kc + 1) * WCHUNK;
                    for (int idx = tid; idx < 218 * 8; idx += NTHR) {
                        int row = idx >> 3, seg = idx & 7;
                        int rg = v0 + row; if (rg > V - 1) rg = V - 1;
                        cpa16((uint32_t)__cvta_generic_to_shared(
                                  Wn + (row & 1) * WTILE + (row >> 1) * WPADF + seg * 4),
                              gsrc + (size_t)rg * H + seg * 4);
                    }
                }
                CP_COMMIT();

                const float* We = W_s + (kc & 1) * WBUF + rp_c * WPADF;  // row 2rp
                const float* Wo = We + WTILE;                            // row 2rp+1
                const float* hb = h_s + (kc << 5);
#pragma unroll
                for (int q = 0; q < 8; q++) {
                    ulonglong2 w0 = *(const ulonglong2*)(We + q * 4);
                    ulonglong2 w1 = *(const ulonglong2*)(Wo + q * 4);
                    const int qs = (q ^ bq) << 2;
#pragma unroll
                    for (int i = 0; i < 4; i++) {
                        ulonglong2 hv = *(const ulonglong2*)(hb + ((bq * 4 + i) << 9) + qs);
                        acc[0][i] = fma2(w0.x, hv.x, acc[0][i]);
                        acc[0][i] = fma2(w0.y, hv.y, acc[0][i]);
                        acc[1][i] = fma2(w1.x, hv.x, acc[1][i]);
                        acc[1][i] = fma2(w1.y, hv.y, acc[1][i]);
                    }
                }
            }

            // epilogue: stores + per-batch argmax candidates
            const int r0  = rp_c * 2;
            const int vv  = v0 + r0;
            const bool val0 = (rp <= RP_MAX) && (vv < V);
            const bool val1 = (rp <= RP_MAX) && (r0 + 1 < ROWS_TOT) && (vv + 1 < V);
            const float bias0 = val0 ? bp[vv] : 0.f;
            const float bias1 = val1 ? bp[vv + 1] : 0.f;
#pragma unroll
            for (int i = 0; i < 4; i++) {
                const int b = bq * 4 + i;
                u64 pk = 0ull;
                if (val0) {
                    float2 f = unpk(acc[0][i]);
                    float l0 = f.x + f.y + bias0;
                    __stcs(&out[((size_t)b * T + t) * (size_t)V + vv], l0);
                    unsigned u0 = __float_as_uint(l0);
                    u0 = (u0 & 0x80000000u) ? ~u0 : (u0 | 0x80000000u);
                    pk = ((u64)u0 << 32) | (unsigned)(~vv);
                }
                if (val1) {
                    float2 f = unpk(acc[1][i]);
                    float l1 = f.x + f.y + bias1;
                    __stcs(&out[((size_t)b * T + t) * (size_t)V + vv + 1], l1);
                    unsigned u1 = __float_as_uint(l1);
                    u1 = (u1 & 0x80000000u) ? ~u1 : (u1 | 0x80000000u);
                    u64 p1 = ((u64)u1 << 32) | (unsigned)(~(vv + 1));
                    if (p1 > pk) pk = p1;
                }
                // reduce across the 8 lanes sharing this bq (strides 4,8,16)
#pragma unroll
                for (int off = 4; off <= 16; off <<= 1) {
                    u64 q = __shfl_xor_sync(0xffffffffu, pk, off);
                    if (q > pk) pk = q;
                }
                if (lane < 4) s_best[lane * 4 + i][warp] = pk;   // lane == bq
            }
            __syncthreads();
            if (tid < B) {
                u64 pk = s_best[tid][0];
#pragma unroll
                for (int w = 1; w < 16; w++) {
                    u64 q = s_best[tid][w];
                    if (q > pk) pk = q;
                }
                atomicMax(&g_amax[p][tid], pk);
            }
        }
        bar_spin(&g_cnt, NBLK * (++full_t));
    }
}

// ---------------- launch ----------------
extern "C" void kernel_launch(void* const* d_in, const int* in_sizes, int n_in,
                              void* d_out, int out_size) {
    const float* x   = (const float*)d_in[0];
    const float* Wt  = (const float*)d_in[1];
    const float* bp  = (const float*)d_in[2];
    const float* Wih = (const float*)d_in[3];
    const float* Whh = (const float*)d_in[4];
    const float* bih = (const float*)d_in[5];
    const float* bhh = (const float*)d_in[6];
    float* out = (float*)d_out;

    const int T = out_size / (B * V);
    if (T <= 0) return;

    cudaFuncSetAttribute(decoder_kernel,
                         cudaFuncAttributeMaxDynamicSharedMemorySize, SMEM_BYTES);

    init_kernel<<<32, 256>>>();
    decoder_kernel<<<NBLK, NTHR, SMEM_BYTES>>>(x, Wt, bp, Wih, Whh, bih, bhh, out, T);
}